// round 1
// baseline (speedup 1.0000x reference)
#include <cuda_runtime.h>
#include <stdint.h>

// PointPillars BEV scatter: (M,3) coords + (M,64) features -> (B,64,496,432)
#define BEV_H 496
#define BEV_W 432
#define NB    4
#define NC    64

// Scratch: inverse map from BEV cell -> pillar index + 1 (0 = empty).
// 4*496*432 ints = 3.43 MB. Device global (no allocations allowed).
__device__ int g_map[NB * BEV_H * BEV_W];

// ---------------------------------------------------------------------------
// Kernel 1: zero the map (int4 vectorized). N4 = NB*H*W/4 = 214272.
__global__ void zero_map_kernel() {
    const int n4 = (NB * BEV_H * BEV_W) / 4;
    int i = blockIdx.x * blockDim.x + threadIdx.x;
    if (i < n4) {
        reinterpret_cast<int4*>(g_map)[i] = make_int4(0, 0, 0, 0);
    }
}

// ---------------------------------------------------------------------------
// Kernel 2: scatter pillar index+1 into the map. Coords are collision-free.
__global__ void scatter_idx_kernel(const int* __restrict__ coords, int M) {
    int m = blockIdx.x * blockDim.x + threadIdx.x;
    if (m < M) {
        int b = coords[3 * m + 0];
        int y = coords[3 * m + 1];
        int x = coords[3 * m + 2];
        g_map[(b * BEV_H + y) * BEV_W + x] = m + 1;
    }
}

// ---------------------------------------------------------------------------
// Kernel 3: dense coalesced gather. Each thread owns 4 consecutive x cells of
// one (b, y) row and emits one float4 store per channel. Output rows are
// 432*4 = 1728 bytes (16B multiple), so float4/int4 accesses are aligned.
// grid = (H/4, B), block = (112, 4); lanes with tx >= 108 idle (W/4 = 108).
__global__ __launch_bounds__(448) void gather_kernel(
    const float* __restrict__ feat, float* __restrict__ out) {
    const int tx = threadIdx.x;
    if (tx >= BEV_W / 4) return;
    const int b  = blockIdx.y;
    const int y  = blockIdx.x * 4 + threadIdx.y;
    const int x4 = tx * 4;

    const int4 mp = *reinterpret_cast<const int4*>(
        &g_map[(b * BEV_H + y) * BEV_W + x4]);

    const float* f0 = mp.x ? feat + (size_t)(mp.x - 1) * NC : nullptr;
    const float* f1 = mp.y ? feat + (size_t)(mp.y - 1) * NC : nullptr;
    const float* f2 = mp.z ? feat + (size_t)(mp.z - 1) * NC : nullptr;
    const float* f3 = mp.w ? feat + (size_t)(mp.w - 1) * NC : nullptr;

    float* outp = out + ((size_t)(b * NC) * BEV_H + y) * BEV_W + x4;
    const size_t cstride = (size_t)BEV_H * BEV_W;

#pragma unroll 8
    for (int c = 0; c < NC; ++c) {
        float4 v;
        v.x = f0 ? __ldg(f0 + c) : 0.0f;
        v.y = f1 ? __ldg(f1 + c) : 0.0f;
        v.z = f2 ? __ldg(f2 + c) : 0.0f;
        v.w = f3 ? __ldg(f3 + c) : 0.0f;
        *reinterpret_cast<float4*>(outp) = v;
        outp += cstride;
    }
}

// ---------------------------------------------------------------------------
extern "C" void kernel_launch(void* const* d_in, const int* in_sizes, int n_in,
                              void* d_out, int out_size) {
    const int*   coords = (const int*)d_in[0];    // (M, 3) int32
    const float* feat   = (const float*)d_in[1];  // (M, 64) float32
    float*       out    = (float*)d_out;          // (4, 64, 496, 432) float32
    const int M = in_sizes[0] / 3;

    // 1) clear inverse map
    {
        const int n4 = (NB * BEV_H * BEV_W) / 4;
        zero_map_kernel<<<(n4 + 255) / 256, 256>>>();
    }
    // 2) scatter pillar indices
    scatter_idx_kernel<<<(M + 255) / 256, 256>>>(coords, M);
    // 3) dense gather into output
    {
        dim3 grid(BEV_H / 4, NB);
        dim3 block(112, 4);
        gather_kernel<<<grid, block>>>(feat, out);
    }
}